// round 16
// baseline (speedup 1.0000x reference)
#include <cuda_runtime.h>
#include <cuda_fp16.h>
#include <stdint.h>

#define N_NODES 50000
#define N_EDGES 50000
#define IN_C 256
#define HID_C 128
#define OUT_C 64
#define MAX_NNZ 800000

// ---------------- scratch (no allocations allowed) ----------------
__device__ __half g_h0h[(size_t)N_NODES * HID_C];  // x @ W1 (fp16)
__device__ __half g_h1h[(size_t)N_NODES * OUT_C];  // f1 @ W2 (fp16)
__device__ __half g_mh [(size_t)N_EDGES * HID_C];  // edge buffer (fp16, reused at C=64)
__device__ float g_dinv[N_NODES];
__device__ float g_binv[N_EDGES];

__device__ int g_cnt[4 * N_EDGES];   // [ecnt | ncnt | ecur | ncur]
__device__ int g_eoff[N_EDGES + 1];
__device__ int g_noff[N_NODES + 1];
__device__ int g_eadj[MAX_NNZ];
__device__ int g_nadj[MAX_NNZ];

// ---------------- histogram ----------------
__global__ void hist_kernel(const int* __restrict__ node_idx,
                            const int* __restrict__ edge_idx,
                            int* __restrict__ ncnt, int* __restrict__ ecnt, int nnz) {
    int t = blockIdx.x * blockDim.x + threadIdx.x;
    if (t < nnz) {
        atomicAdd(&ncnt[node_idx[t]], 1);
        atomicAdd(&ecnt[edge_idx[t]], 1);
    }
}

// ---------------- exclusive scan + fused 1/count ----------------
__global__ void scan_kernel(const int* __restrict__ cntE, int* __restrict__ offE,
                            const int* __restrict__ cntN, int* __restrict__ offN,
                            float* __restrict__ binv, float* __restrict__ dinv, int n) {
    const int* cnt = (blockIdx.x == 0) ? cntE : cntN;
    int* off       = (blockIdx.x == 0) ? offE : offN;
    float* inv     = (blockIdx.x == 0) ? binv : dinv;
    __shared__ int sh[1024];
    int tid = threadIdx.x;
    int chunk = (n + 1023) / 1024;
    int start = tid * chunk;
    int end = min(start + chunk, n);
    int s = 0;
    for (int i = start; i < end; i++) {
        int c = cnt[i];
        s += c;
        inv[i] = (c > 0) ? (1.0f / (float)c) : 0.0f;
    }
    sh[tid] = s;
    __syncthreads();
    for (int d = 1; d < 1024; d <<= 1) {
        int v = (tid >= d) ? sh[tid - d] : 0;
        __syncthreads();
        sh[tid] += v;
        __syncthreads();
    }
    int run = (tid == 0) ? 0 : sh[tid - 1];
    for (int i = start; i < end; i++) {
        off[i] = run;
        run += cnt[i];
    }
    if (tid == 1023) off[n] = sh[1023];
}

// ---------------- CSR fill ----------------
__global__ void fill_kernel(const int* __restrict__ node_idx, const int* __restrict__ edge_idx,
                            const int* __restrict__ eoff, const int* __restrict__ noff,
                            int* __restrict__ ecur, int* __restrict__ ncur,
                            int* __restrict__ eadj, int* __restrict__ nadj, int nnz) {
    int t = blockIdx.x * blockDim.x + threadIdx.x;
    if (t < nnz) {
        int nd = node_idx[t];
        int eg = edge_idx[t];
        int p = atomicAdd(&ecur[eg], 1);
        eadj[eoff[eg] + p] = nd;
        int q = atomicAdd(&ncur[nd], 1);
        nadj[noff[nd] + q] = eg;
    }
}

// ---------------- gather-reduce: one warp per 64-channel chunk, 8x unroll ----------------
// CHUNKS = C/64. warp w -> row = w/CHUNKS, chunk = w%CHUNKS.
// Each lane: one half2 per neighbor (warp = one 128B line per neighbor).
// FINAL=false: out fp16 (edge pass, no scale).
// FINAL=true:  gather scaled by sscale[nb], then *rscale[row]+bias, relu, out fp32.
template <int CHUNKS, bool FINAL>
__global__ void agg_k(const __half* __restrict__ src, const int* __restrict__ adj,
                      const int* __restrict__ off, const float* __restrict__ sscale,
                      void* __restrict__ outv, const float* __restrict__ rscale,
                      const float* __restrict__ bias, int rows) {
    int w = (blockIdx.x * blockDim.x + threadIdx.x) >> 5;
    int lane = threadIdx.x & 31;
    if (w >= rows * CHUNKS) return;
    int row = w / CHUNKS;
    int ch = w - row * CHUNKS;
    const int C = CHUNKS * 64;
    int lo = ch * 64 + lane * 2;

    int s0 = off[row];
    int s1 = off[row + 1];

    float a0 = 0.0f, a1 = 0.0f;

    int j = s0;
    for (; j + 8 <= s1; j += 8) {
        int nb[8];
#pragma unroll
        for (int q = 0; q < 8; q++) nb[q] = adj[j + q];
        __half2 v[8];
#pragma unroll
        for (int q = 0; q < 8; q++)
            v[q] = *reinterpret_cast<const __half2*>(src + (size_t)nb[q] * C + lo);
        if (FINAL) {
            float sc[8];
#pragma unroll
            for (int q = 0; q < 8; q++) sc[q] = sscale[nb[q]];
#pragma unroll
            for (int q = 0; q < 8; q++) {
                float2 f = __half22float2(v[q]);
                a0 += f.x * sc[q];
                a1 += f.y * sc[q];
            }
        } else {
#pragma unroll
            for (int q = 0; q < 8; q++) {
                float2 f = __half22float2(v[q]);
                a0 += f.x;
                a1 += f.y;
            }
        }
    }
    for (; j < s1; j++) {
        int nb = adj[j];
        float2 f = __half22float2(*reinterpret_cast<const __half2*>(src + (size_t)nb * C + lo));
        if (FINAL) {
            float sc = sscale[nb];
            a0 += f.x * sc;
            a1 += f.y * sc;
        } else {
            a0 += f.x;
            a1 += f.y;
        }
    }

    if (FINAL) {
        float rs = rscale[row];
        a0 = fmaxf(a0 * rs + bias[lo], 0.0f);
        a1 = fmaxf(a1 * rs + bias[lo + 1], 0.0f);
        float* out = (float*)outv;
        *reinterpret_cast<float2*>(out + (size_t)row * C + lo) = make_float2(a0, a1);
    } else {
        __half* out = (__half*)outv;
        *reinterpret_cast<__half2*>(out + (size_t)row * C + lo) = __floats2half2_rn(a0, a1);
    }
}

// ---------------- fp16 tensor-core GEMM (m16n8k16, fp32 accumulate) ----------------
__device__ __forceinline__ void mma_f16(float* c, const uint32_t* a, const uint32_t* b) {
    asm("mma.sync.aligned.m16n8k16.row.col.f32.f16.f16.f32 "
        "{%0,%1,%2,%3}, {%4,%5,%6,%7}, {%8,%9}, {%0,%1,%2,%3};"
        : "+f"(c[0]), "+f"(c[1]), "+f"(c[2]), "+f"(c[3])
        : "r"(a[0]), "r"(a[1]), "r"(a[2]), "r"(a[3]), "r"(b[0]), "r"(b[1]));
}

// C[M,N] = A[M,K] @ B[K,N] (+bias fp32 path). BM=128, BN=64, BK=32, 256 threads (8 warps 4x2).
template <bool HALF_OUT>
__global__ void __launch_bounds__(256)
f16_gemm(const float* __restrict__ A, const float* __restrict__ B,
         void* __restrict__ Cv, int M, int N, int K,
         const float* __restrict__ bias) {
    const int BM = 128, BN = 64, BK = 32;
    const int ASH = BK + 8;    // 40 halves row stride
    const int BSH = BK + 2;    // 34 halves row stride
    __shared__ __half Ah[BM][ASH];
    __shared__ __half Bh[BN][BSH];

    int tid = threadIdx.x;
    int wid = tid >> 5;
    int lane = tid & 31;
    int gid = lane >> 2;
    int tg = lane & 3;
    int warp_m = wid >> 1;
    int warp_n = wid & 1;
    int mb = warp_m * 32;
    int nb = warp_n * 32;

    int rowBase = blockIdx.x * BM;
    int colBase = blockIdx.y * BN;

    float acc[2][4][4];
#pragma unroll
    for (int t = 0; t < 2; t++)
#pragma unroll
        for (int u = 0; u < 4; u++)
#pragma unroll
            for (int k = 0; k < 4; k++) acc[t][u][k] = 0.0f;

    for (int k0 = 0; k0 < K; k0 += BK) {
#pragma unroll
        for (int it = 0; it < 4; it++) {
            int idx = tid * 4 + it * 1024;
            int r = idx / BK;
            int c = idx % BK;
            int gr = rowBase + r;
            float4 v = make_float4(0.f, 0.f, 0.f, 0.f);
            if (gr < M)
                v = *reinterpret_cast<const float4*>(A + (size_t)gr * K + k0 + c);
            *reinterpret_cast<__half2*>(&Ah[r][c])     = __floats2half2_rn(v.x, v.y);
            *reinterpret_cast<__half2*>(&Ah[r][c + 2]) = __floats2half2_rn(v.z, v.w);
        }
#pragma unroll
        for (int it = 0; it < 2; it++) {
            int idx = tid * 4 + it * 1024;
            int r = idx / BN;
            int c = idx % BN;
            float4 v = *reinterpret_cast<const float4*>(B + (size_t)(k0 + r) * N + colBase + c);
            Bh[c + 0][r] = __float2half(v.x);
            Bh[c + 1][r] = __float2half(v.y);
            Bh[c + 2][r] = __float2half(v.z);
            Bh[c + 3][r] = __float2half(v.w);
        }
        __syncthreads();

#pragma unroll
        for (int ks = 0; ks < 2; ks++) {
            int kk = ks * 16 + tg * 2;
            uint32_t af[2][4];
#pragma unroll
            for (int t = 0; t < 2; t++) {
                int m = mb + t * 16 + gid;
                af[t][0] = *reinterpret_cast<const uint32_t*>(&Ah[m][kk]);
                af[t][1] = *reinterpret_cast<const uint32_t*>(&Ah[m + 8][kk]);
                af[t][2] = *reinterpret_cast<const uint32_t*>(&Ah[m][kk + 8]);
                af[t][3] = *reinterpret_cast<const uint32_t*>(&Ah[m + 8][kk + 8]);
            }
            uint32_t bf[4][2];
#pragma unroll
            for (int u = 0; u < 4; u++) {
                int n = nb + u * 8 + gid;
                bf[u][0] = *reinterpret_cast<const uint32_t*>(&Bh[n][kk]);
                bf[u][1] = *reinterpret_cast<const uint32_t*>(&Bh[n][kk + 8]);
            }
#pragma unroll
            for (int t = 0; t < 2; t++)
#pragma unroll
                for (int u = 0; u < 4; u++)
                    mma_f16(acc[t][u], af[t], bf[u]);
        }
        __syncthreads();
    }

#pragma unroll
    for (int t = 0; t < 2; t++) {
#pragma unroll
        for (int u = 0; u < 4; u++) {
            int row = rowBase + mb + t * 16 + gid;
            int col = colBase + nb + u * 8 + tg * 2;
            if (HALF_OUT) {
                __half* C = (__half*)Cv;
                if (row < M)
                    *reinterpret_cast<__half2*>(C + (size_t)row * N + col) =
                        __floats2half2_rn(acc[t][u][0], acc[t][u][1]);
                if (row + 8 < M)
                    *reinterpret_cast<__half2*>(C + (size_t)(row + 8) * N + col) =
                        __floats2half2_rn(acc[t][u][2], acc[t][u][3]);
            } else {
                float* C = (float*)Cv;
                float b0 = 0.f, b1 = 0.f;
                if (bias) { b0 = bias[col]; b1 = bias[col + 1]; }
                if (row < M) {
                    float2 v = make_float2(acc[t][u][0] + b0, acc[t][u][1] + b1);
                    *reinterpret_cast<float2*>(C + (size_t)row * N + col) = v;
                }
                if (row + 8 < M) {
                    float2 v = make_float2(acc[t][u][2] + b0, acc[t][u][3] + b1);
                    *reinterpret_cast<float2*>(C + (size_t)(row + 8) * N + col) = v;
                }
            }
        }
    }
}

// ---------------- launch ----------------
extern "C" void kernel_launch(void* const* d_in, const int* in_sizes, int n_in,
                              void* d_out, int out_size) {
    const float* x    = (const float*)d_in[0];
    const int*   hidx = (const int*)d_in[1];   // int32 on device (JAX x64 disabled)
    const float* W1   = (const float*)d_in[2];
    const float* b1   = (const float*)d_in[3];
    const float* W2   = (const float*)d_in[4];
    const float* b2   = (const float*)d_in[5];
    const float* Wp   = (const float*)d_in[6];
    const float* bp   = (const float*)d_in[7];

    int nnz = in_sizes[1] / 2;
    const int* node_idx = hidx;
    const int* edge_idx = hidx + nnz;

    // output layout: (z [N,64], features_1 [N,128], features_2 [N,64])
    float* z  = (float*)d_out;
    float* f1 = z  + (size_t)N_NODES * OUT_C;
    float* f2 = f1 + (size_t)N_NODES * HID_C;

    __half *p_h0h, *p_h1h, *p_mh;
    float *p_dinv, *p_binv;
    int *p_cnt, *p_eoff, *p_noff, *p_eadj, *p_nadj;
    cudaGetSymbolAddress((void**)&p_h0h,  g_h0h);
    cudaGetSymbolAddress((void**)&p_h1h,  g_h1h);
    cudaGetSymbolAddress((void**)&p_mh,   g_mh);
    cudaGetSymbolAddress((void**)&p_dinv, g_dinv);
    cudaGetSymbolAddress((void**)&p_binv, g_binv);
    cudaGetSymbolAddress((void**)&p_cnt,  g_cnt);
    cudaGetSymbolAddress((void**)&p_eoff, g_eoff);
    cudaGetSymbolAddress((void**)&p_noff, g_noff);
    cudaGetSymbolAddress((void**)&p_eadj, g_eadj);
    cudaGetSymbolAddress((void**)&p_nadj, g_nadj);

    int* p_ecnt = p_cnt;
    int* p_ncnt = p_cnt + N_EDGES;
    int* p_ecur = p_cnt + 2 * N_EDGES;
    int* p_ncur = p_cnt + 3 * N_EDGES;

    static cudaStream_t s_csr = nullptr;
    static cudaEvent_t ev_fork = nullptr, ev_join = nullptr;
    if (!s_csr) {
        cudaStreamCreateWithFlags(&s_csr, cudaStreamNonBlocking);
        cudaEventCreateWithFlags(&ev_fork, cudaEventDisableTiming);
        cudaEventCreateWithFlags(&ev_join, cudaEventDisableTiming);
    }

    dim3 ggrid((N_NODES + 127) / 128, 1);

    // ---- fork: CSR build on side stream, gemm1 on main stream ----
    cudaEventRecord(ev_fork, 0);
    cudaStreamWaitEvent(s_csr, ev_fork, 0);

    cudaMemsetAsync(p_cnt, 0, 4 * N_EDGES * sizeof(int), s_csr);
    hist_kernel<<<(nnz + 255) / 256, 256, 0, s_csr>>>(node_idx, edge_idx, p_ncnt, p_ecnt, nnz);
    scan_kernel<<<2, 1024, 0, s_csr>>>(p_ecnt, p_eoff, p_ncnt, p_noff, p_binv, p_dinv, N_EDGES);
    fill_kernel<<<(nnz + 255) / 256, 256, 0, s_csr>>>(node_idx, edge_idx, p_eoff, p_noff,
                                                      p_ecur, p_ncur, p_eadj, p_nadj, nnz);
    cudaEventRecord(ev_join, s_csr);

    // ---- layer 1: h0 = x @ W1 (fp16 out) ---- (M=50000, N=128, K=256)
    {
        dim3 grid((N_NODES + 127) / 128, HID_C / 64);
        f16_gemm<true><<<grid, 256>>>(x, W1, p_h0h, N_NODES, HID_C, IN_C, nullptr);
    }

    // ---- join: aggregation needs both gemm1 and the CSR ----
    cudaStreamWaitEvent(0, ev_join, 0);

    // layer 1 aggregation (C=128 -> CHUNKS=2)
    {
        int warps = N_EDGES * 2;
        int blocks = (warps * 32 + 255) / 256;
        agg_k<2, false><<<blocks, 256>>>(p_h0h, p_eadj, p_eoff, nullptr,
                                         p_mh, nullptr, nullptr, N_EDGES);
        agg_k<2, true><<<blocks, 256>>>(p_mh, p_nadj, p_noff, p_binv,
                                        f1, p_dinv, b1, N_NODES);
    }

    // ---- layer 2: h1 = f1 @ W2 (fp16 out) ---- (M=50000, N=64, K=128)
    f16_gemm<true><<<ggrid, 256>>>(f1, W2, p_h1h, N_NODES, OUT_C, HID_C, nullptr);
    {
        int warps = N_EDGES;
        int blocks = (warps * 32 + 255) / 256;
        agg_k<1, false><<<blocks, 256>>>(p_h1h, p_eadj, p_eoff, nullptr,
                                         p_mh, nullptr, nullptr, N_EDGES);
        agg_k<1, true><<<blocks, 256>>>(p_mh, p_nadj, p_noff, p_binv,
                                        f2, p_dinv, b2, N_NODES);
    }

    // ---- projection: z = f2 @ Wp + bp (fp32 out) ---- (M=50000, N=64, K=64)
    f16_gemm<false><<<ggrid, 256>>>(f2, Wp, z, N_NODES, OUT_C, OUT_C, bp);
}